// round 15
// baseline (speedup 1.0000x reference)
#include <cuda_runtime.h>

#define NNODES 100000
#define NEDGES 1250000
#define NGRAPH 256
#define H      64
#define NCLS   10
#define MAXBLK 512

// ---- scratch (static device globals; no allocation) ----
__device__ float g_bufA[NNODES * H];
__device__ float g_bufB[NNODES * H];
__device__ int   g_degi[NNODES];       // in-degree (excluding self loop)
__device__ float g_dinv[NNODES];
__device__ int   g_rowptr[NNODES];     // CSR row starts (by dst)
__device__ int   g_cursor[NNODES];
__device__ int2  g_epack[NEDGES];      // CSR slot: {src, norm as bits}
__device__ int   g_bsum[MAXBLK];
__device__ int   g_boff[MAXBLK];
__device__ float g_pool[NGRAPH * H];
__device__ float g_cnt[NGRAPH];

__device__ __forceinline__ void red_add_v2(float* p, float a, float b) {
    asm volatile("red.global.add.v2.f32 [%0], {%1,%2};"
                 :: "l"(p), "f"(a), "f"(b) : "memory");
}

// ---- init ----
__global__ void __launch_bounds__(256) k_init(int n) {
    int i = blockIdx.x * blockDim.x + threadIdx.x;
    if (i < n)           g_degi[i] = 0;
    if (i < NGRAPH * H)  g_pool[i] = 0.0f;
    if (i < NGRAPH)      g_cnt[i]  = 0.0f;
}

// ---- in-degree histogram ----
__global__ void __launch_bounds__(256) k_deg(const int* __restrict__ ei, int ne, int n) {
    int e = blockIdx.x * blockDim.x + threadIdx.x;
    if (e >= ne) return;
    int d = ei[ne + e];
    if ((unsigned)d < (unsigned)n) atomicAdd(&g_degi[d], 1);
}

// ---- block-wise exclusive scan of degi ----
__global__ void __launch_bounds__(256) k_scan1(int n) {
    __shared__ int sh[256];
    int tid = threadIdx.x;
    int i = blockIdx.x * 256 + tid;
    int v = (i < n) ? g_degi[i] : 0;
    sh[tid] = v;
    __syncthreads();
    #pragma unroll
    for (int off = 1; off < 256; off <<= 1) {
        int t = (tid >= off) ? sh[tid - off] : 0;
        __syncthreads();
        sh[tid] += t;
        __syncthreads();
    }
    if (i < n) g_rowptr[i] = sh[tid] - v;
    if (tid == 255) g_bsum[blockIdx.x] = sh[255];
}

__global__ void __launch_bounds__(MAXBLK) k_scan2(int nb) {
    __shared__ int sh[MAXBLK];
    int t = threadIdx.x;
    int v = (t < nb) ? g_bsum[t] : 0;
    sh[t] = v;
    __syncthreads();
    #pragma unroll
    for (int off = 1; off < MAXBLK; off <<= 1) {
        int u = (t >= off) ? sh[t - off] : 0;
        __syncthreads();
        sh[t] += u;
        __syncthreads();
    }
    if (t < nb) g_boff[t] = sh[t] - v;
}

__global__ void __launch_bounds__(256) k_scan3(int n) {
    int i = blockIdx.x * blockDim.x + threadIdx.x;
    if (i >= n) return;
    int rp = g_rowptr[i] + g_boff[i >> 8];
    g_rowptr[i] = rp;
    g_cursor[i] = rp;
    g_dinv[i]   = rsqrtf(1.0f + (float)g_degi[i]);   // +1 self loop
}

// ---- fill CSR slots (slot order within node irrelevant) ----
__global__ void __launch_bounds__(256) k_fill(const int* __restrict__ ei, int ne, int n) {
    int e = blockIdx.x * blockDim.x + threadIdx.x;
    if (e >= ne) return;
    int s = ei[e];
    int d = ei[ne + e];
    if ((unsigned)d >= (unsigned)n) return;
    int slot = atomicAdd(&g_cursor[d], 1);
    float nrm = 0.0f;
    int   ss  = 0;
    if ((unsigned)s < (unsigned)n) { nrm = g_dinv[s] * g_dinv[d]; ss = s; }
    g_epack[slot] = make_int2(ss, __float_as_int(nrm));
}

// ---- layer-1 GEMM: out = x @ W1 (16 rows/block) ----
__global__ void __launch_bounds__(256) k_gemm(
        const float* __restrict__ in, const float* __restrict__ W,
        float* __restrict__ out, int n) {
    __shared__ float sW[64 * 64];
    __shared__ float sIn[16][64];
    int t = threadIdx.x;
    #pragma unroll
    for (int i = 0; i < 16; i++) sW[t + i * 256] = W[t + i * 256];
    int row0 = blockIdx.x * 16;
    {
        int r  = t >> 4;
        int c4 = t & 15;
        int gr = row0 + r;
        float4 v = make_float4(0.f, 0.f, 0.f, 0.f);
        if (gr < n) v = reinterpret_cast<const float4*>(in)[gr * 16 + c4];
        sIn[r][c4 * 4 + 0] = v.x;
        sIn[r][c4 * 4 + 1] = v.y;
        sIn[r][c4 * 4 + 2] = v.z;
        sIn[r][c4 * 4 + 3] = v.w;
    }
    __syncthreads();
    int col = t & 63;
    int rb  = t >> 6;
    float a0 = 0.f, a1 = 0.f, a2 = 0.f, a3 = 0.f;
    #pragma unroll
    for (int k = 0; k < 64; k++) {
        float w = sW[k * 64 + col];
        a0 += sIn[rb     ][k] * w;
        a1 += sIn[rb +  4][k] * w;
        a2 += sIn[rb +  8][k] * w;
        a3 += sIn[rb + 12][k] * w;
    }
    if (row0 + rb      < n) out[(row0 + rb     ) * 64 + col] = a0;
    if (row0 + rb +  4 < n) out[(row0 + rb +  4) * 64 + col] = a1;
    if (row0 + rb +  8 < n) out[(row0 + rb +  8) * 64 + col] = a2;
    if (row0 + rb + 12 < n) out[(row0 + rb + 12) * 64 + col] = a3;
}

// ---- per-warp node aggregation: agg = dinv^2*in[node] + sum(nrm*in[src]) ----
__device__ __forceinline__ float2 warp_aggregate(
        const float* __restrict__ in, int node, int lane) {
    int beg = g_rowptr[node];
    int end = beg + g_degi[node];
    float d = g_dinv[node];
    float c = d * d;
    float2 s = reinterpret_cast<const float2*>(in + node * 64)[lane];
    float ax = c * s.x, ay = c * s.y;
    int i = beg;
    for (; i + 4 <= end; i += 4) {
        int2 p0 = __ldg(&g_epack[i]);
        int2 p1 = __ldg(&g_epack[i + 1]);
        int2 p2 = __ldg(&g_epack[i + 2]);
        int2 p3 = __ldg(&g_epack[i + 3]);
        float2 v0 = __ldg(reinterpret_cast<const float2*>(in + p0.x * 64) + lane);
        float2 v1 = __ldg(reinterpret_cast<const float2*>(in + p1.x * 64) + lane);
        float2 v2 = __ldg(reinterpret_cast<const float2*>(in + p2.x * 64) + lane);
        float2 v3 = __ldg(reinterpret_cast<const float2*>(in + p3.x * 64) + lane);
        float w0 = __int_as_float(p0.y), w1 = __int_as_float(p1.y);
        float w2 = __int_as_float(p2.y), w3 = __int_as_float(p3.y);
        ax += w0 * v0.x + w1 * v1.x + w2 * v2.x + w3 * v3.x;
        ay += w0 * v0.y + w1 * v1.y + w2 * v2.y + w3 * v3.y;
    }
    for (; i < end; i++) {
        int2 p0 = __ldg(&g_epack[i]);
        float2 v0 = __ldg(reinterpret_cast<const float2*>(in + p0.x * 64) + lane);
        float w0 = __int_as_float(p0.y);
        ax += w0 * v0.x;
        ay += w0 * v0.y;
    }
    return make_float2(ax, ay);
}

// ---- fused: aggregate -> (+bias, relu) -> @W -> out. 8 nodes/block ----
__global__ void __launch_bounds__(256) k_gather_gemm(
        const float* __restrict__ in, const float* __restrict__ bias,
        const float* __restrict__ W, float* __restrict__ out, int n) {
    __shared__ float sW[64 * 64];
    __shared__ float sH[8][64];
    int t    = threadIdx.x;
    int w    = t >> 5;
    int lane = t & 31;
    int node = blockIdx.x * 8 + w;
    #pragma unroll
    for (int i = 0; i < 16; i++) sW[t + i * 256] = W[t + i * 256];
    __syncthreads();

    bool valid = (node < n);
    if (valid) {
        float2 a = warp_aggregate(in, node, lane);
        float2 b = reinterpret_cast<const float2*>(bias)[lane];
        a.x = fmaxf(a.x + b.x, 0.0f);
        a.y = fmaxf(a.y + b.y, 0.0f);
        reinterpret_cast<float2*>(sH[w])[lane] = a;
    }
    __syncwarp();
    if (valid) {
        const float2* sWf2 = reinterpret_cast<const float2*>(sW);
        float y0 = 0.f, y1 = 0.f;
        #pragma unroll
        for (int k = 0; k < 64; k++) {
            float  hk = sH[w][k];
            float2 wv = sWf2[k * 32 + lane];
            y0 += hk * wv.x;
            y1 += hk * wv.y;
        }
        reinterpret_cast<float2*>(out + node * 64)[lane] = make_float2(y0, y1);
    }
}

// ---- fused: aggregate -> (+b3) -> pool red. 8 nodes/block ----
__global__ void __launch_bounds__(256) k_gather_pool(
        const float* __restrict__ in, const float* __restrict__ b3,
        const int* __restrict__ batch, int n) {
    int t    = threadIdx.x;
    int w    = t >> 5;
    int lane = t & 31;
    int node = blockIdx.x * 8 + w;
    if (node >= n) return;
    float2 a = warp_aggregate(in, node, lane);
    float2 b = reinterpret_cast<const float2*>(b3)[lane];
    a.x += b.x;
    a.y += b.y;
    int g = batch[node];
    if ((unsigned)g >= (unsigned)NGRAPH) return;
    red_add_v2(g_pool + g * 64 + lane * 2, a.x, a.y);
    if (lane == 0) atomicAdd(&g_cnt[g], 1.0f);
}

// ---- final linear ----
__global__ void __launch_bounds__(64) k_final(
        const float* __restrict__ Wlin,
        const float* __restrict__ blin,
        float* __restrict__ out) {
    __shared__ float sp[64];
    int g = blockIdx.x;
    int t = threadIdx.x;
    float inv = 1.0f / fmaxf(g_cnt[g], 1.0f);
    sp[t] = g_pool[g * 64 + t] * inv;
    __syncthreads();
    if (t < NCLS) {
        float s = blin[t];
        #pragma unroll
        for (int k = 0; k < 64; k++) s += sp[k] * Wlin[k * NCLS + t];
        out[g * NCLS + t] = s;
    }
}

extern "C" void kernel_launch(void* const* d_in, const int* in_sizes, int n_in,
                              void* d_out, int out_size) {
    const float* x     = (const float*)d_in[0];
    const int*   ei    = (const int*)d_in[1];     // int32 (JAX x64 disabled)
    const int*   batch = (const int*)d_in[2];     // int32
    const float* W1    = (const float*)d_in[3];
    const float* b1    = (const float*)d_in[4];
    const float* W2    = (const float*)d_in[5];
    const float* b2    = (const float*)d_in[6];
    const float* W3    = (const float*)d_in[7];
    const float* b3    = (const float*)d_in[8];
    const float* Wlin  = (const float*)d_in[9];
    const float* blin  = (const float*)d_in[10];
    float* out = (float*)d_out;

    int n  = in_sizes[0] / H;     // 100000
    int ne = in_sizes[1] / 2;     // 1250000

    float* bufA; cudaGetSymbolAddress((void**)&bufA, g_bufA);
    float* bufB; cudaGetSymbolAddress((void**)&bufB, g_bufB);

    const int T = 256;
    int nb_n    = (n + T - 1) / T;
    int nb_e    = (ne + T - 1) / T;
    int nb_g    = (n + 15) / 16;
    int nb_scan = (n + 255) / 256;                 // 391 <= MAXBLK
    int nb_node = (n + 7) / 8;                     // 8 nodes (warps) / block

    // ---- setup: degree, scan -> CSR rowptr, fill ----
    k_init <<<nb_n, T>>>(n);
    k_deg  <<<nb_e, T>>>(ei, ne, n);
    k_scan1<<<nb_scan, 256>>>(n);
    k_scan2<<<1, MAXBLK>>>(nb_scan);
    k_scan3<<<nb_n, T>>>(n);
    k_fill <<<nb_e, T>>>(ei, ne, n);

    // ---- fused layers ----
    k_gemm       <<<nb_g, 256>>>(x, W1, bufA, n);                  // X @ W1
    k_gather_gemm<<<nb_node, T>>>(bufA, b1, W2, bufB, n);          // agg,+b1,relu,@W2
    k_gather_gemm<<<nb_node, T>>>(bufB, b2, W3, bufA, n);          // agg,+b2,relu,@W3
    k_gather_pool<<<nb_node, T>>>(bufA, b3, batch, n);             // agg,+b3,pool

    k_final<<<NGRAPH, 64>>>(Wlin, blin, out);
}